// round 9
// baseline (speedup 1.0000x reference)
#include <cuda_runtime.h>
#include <cuda_bf16.h>
#include <cstdint>
#include <cstddef>

#define Bq 256
#define Tq 512
#define Dq 64
#define Hq 128
#define NROW (Bq * Tq)
#define TH ((size_t)Tq * Hq)

typedef unsigned long long ull;

// ---------------- packed f32x2 helpers -------------------------------------
__device__ __forceinline__ ull ffma2(ull a, ull b, ull c) {
    ull d;
    asm("fma.rn.f32x2 %0, %1, %2, %3;" : "=l"(d) : "l"(a), "l"(b), "l"(c));
    return d;
}
__device__ __forceinline__ ull pack2(float lo, float hi) {
    ull d;
    asm("mov.b64 %0, {%1, %2};" : "=l"(d) : "f"(lo), "f"(hi));
    return d;
}
__device__ __forceinline__ float2 unpack2(ull v) {
    float2 r;
    asm("mov.b64 {%0, %1}, %2;" : "=f"(r.x), "=f"(r.y) : "l"(v));
    return r;
}
__device__ __forceinline__ float fast_sigmoid(float x) {
    return __fdividef(1.f, 1.f + __expf(-x));
}

// ---------------- scratch (device globals; no runtime allocation) ----------
__device__ float g_Az[(size_t)NROW * Hq];
__device__ float g_Ar[(size_t)NROW * Hq];
__device__ float g_Ah[(size_t)NROW * Hq];
__device__ float g_gh[(size_t)NROW * Hq];

// ---------------- Phase 1: imputation + input projections ------------------
// 64 rows per CTA, 512 threads (16 warps -> 4/SMSP). thread = (j, quarter).
// Each thread computes 16 rows (8 f32x2 row-pairs) for its output column j.
#define RPB 64

__global__ void __launch_bounds__(512) phase1_kernel(
    const float* __restrict__ values, const float* __restrict__ masks,
    const float* __restrict__ deltas, const float* __restrict__ emp,
    const float* __restrict__ xlocf,
    const float* __restrict__ wgx, const float* __restrict__ bgx,
    const float* __restrict__ wgh, const float* __restrict__ bgh,
    const float* __restrict__ wzx, const float* __restrict__ wzm, const float* __restrict__ bz,
    const float* __restrict__ wrx, const float* __restrict__ wrm, const float* __restrict__ br,
    const float* __restrict__ whx, const float* __restrict__ whm, const float* __restrict__ bh)
{
    // [k][r] layout, row stride 64 floats (256B). 3 x 16KB = 48KB static.
    __shared__ alignas(16) float sx[Dq * RPB];
    __shared__ alignas(16) float smm[Dq * RPB];
    __shared__ alignas(16) float sd[Dq * RPB];

    const int tid = threadIdx.x;
    const int row0 = blockIdx.x * RPB;

    // load + impute (coalesced over k); element r of row k at sx[k*64 + r]
    for (int i = tid; i < RPB * Dq; i += 512) {
        int r = i >> 6, k = i & 63;
        size_t g = (size_t)(row0 + r) * Dq + k;
        float x = values[g], m = masks[g], dl = deltas[g], xl = xlocf[g];
        float gx = __expf(-fmaxf(fmaf(wgx[k], dl, bgx[k]), 0.f));
        float xi = m * x + (1.f - m) * (gx * xl + (1.f - gx) * emp[k]);
        sx[(k << 6) + r] = xi;
        smm[(k << 6) + r] = m;
        sd[(k << 6) + r] = dl;
    }
    __syncthreads();

    const int j = tid & 127;
    const int quarter = tid >> 7;       // which 16-row quarter
    const int fofs = quarter * 16;      // float offset within a smem row

    ull accZ[8], accR[8], accH[8], accG[8];
    {
        float bzv = bz[j], brv = br[j], bhv = bh[j], bgv = bgh[j];
#pragma unroll
        for (int p = 0; p < 8; p++) {
            accZ[p] = pack2(bzv, bzv);
            accR[p] = pack2(brv, brv);
            accH[p] = pack2(bhv, bhv);
            accG[p] = pack2(bgv, bgv);
        }
    }

#pragma unroll 4
    for (int k = 0; k < Dq; k++) {
        int wi = k * Hq + j;
        ull wgh2 = pack2(wgh[wi], wgh[wi]);
        ull wzx2 = pack2(wzx[wi], wzx[wi]);
        ull wzm2 = pack2(wzm[wi], wzm[wi]);
        ull wrx2 = pack2(wrx[wi], wrx[wi]);
        ull wrm2 = pack2(wrm[wi], wrm[wi]);
        ull whx2 = pack2(whx[wi], whx[wi]);
        ull whm2 = pack2(whm[wi], whm[wi]);
        const ulonglong2* x2 = (const ulonglong2*)(sx + (k << 6) + fofs);
        const ulonglong2* m2 = (const ulonglong2*)(smm + (k << 6) + fofs);
        const ulonglong2* d2 = (const ulonglong2*)(sd + (k << 6) + fofs);
#pragma unroll
        for (int q = 0; q < 4; q++) {
            ulonglong2 xv = x2[q];
            ulonglong2 mv = m2[q];
            ulonglong2 dv = d2[q];
            accG[2 * q]     = ffma2(dv.x, wgh2, accG[2 * q]);
            accG[2 * q + 1] = ffma2(dv.y, wgh2, accG[2 * q + 1]);
            accZ[2 * q]     = ffma2(xv.x, wzx2, accZ[2 * q]);
            accZ[2 * q + 1] = ffma2(xv.y, wzx2, accZ[2 * q + 1]);
            accR[2 * q]     = ffma2(xv.x, wrx2, accR[2 * q]);
            accR[2 * q + 1] = ffma2(xv.y, wrx2, accR[2 * q + 1]);
            accH[2 * q]     = ffma2(xv.x, whx2, accH[2 * q]);
            accH[2 * q + 1] = ffma2(xv.y, whx2, accH[2 * q + 1]);
            accZ[2 * q]     = ffma2(mv.x, wzm2, accZ[2 * q]);
            accZ[2 * q + 1] = ffma2(mv.y, wzm2, accZ[2 * q + 1]);
            accR[2 * q]     = ffma2(mv.x, wrm2, accR[2 * q]);
            accR[2 * q + 1] = ffma2(mv.y, wrm2, accR[2 * q + 1]);
            accH[2 * q]     = ffma2(mv.x, whm2, accH[2 * q]);
            accH[2 * q + 1] = ffma2(mv.y, whm2, accH[2 * q + 1]);
        }
    }

#pragma unroll
    for (int p = 0; p < 8; p++) {
        int r0 = quarter * 16 + 2 * p;
        size_t o0 = (size_t)(row0 + r0) * Hq + j;
        size_t o1 = o0 + Hq;
        float2 vz = unpack2(accZ[p]);
        float2 vr = unpack2(accR[p]);
        float2 vh = unpack2(accH[p]);
        float2 vg = unpack2(accG[p]);
        g_Az[o0] = vz.x;  g_Az[o1] = vz.y;
        g_Ar[o0] = vr.x;  g_Ar[o1] = vr.y;
        g_Ah[o0] = vh.x;  g_Ah[o1] = vh.y;
        g_gh[o0] = __expf(-fmaxf(vg.x, 0.f));
        g_gh[o1] = __expf(-fmaxf(vg.y, 0.f));
    }
}

// ---------------- Phase 2: persistent recurrence (unrolled pipeline) -------
// 128 CTAs x 384 threads; CTA owns 2 independent batch rows.
// Warp groups: g=0 -> z, g=1 -> r, g=2 -> h; weights register-resident.
// Slot schedule (one barrier per slot, loop unrolled by 2 slots):
//   even slot su:  z/r gates for (row0, t=su/2); h update for (row1, t=su/2-1)
//   odd  slot su+1: z/r gates for (row1, t=su/2); h update for (row0, t=su/2)
// Register sets A (even slots) / B (odd slots): each prefetch LDG lands
// directly in the register consumed two slots later (no shift moves).
// h-warps keep their scaled h in registers (hreg0/hreg1); gamma folded into
// the h epilogue (pre-scale by gamma(t+1)).
#define RPC 2
#define GRID2 (Bq / RPC)

__device__ __forceinline__ float dot1(const float* __restrict__ hp,
                                      const ull* __restrict__ w, float init)
{
    ull a = pack2(init, 0.f);
    ull b = pack2(0.f, 0.f);
    ull c = b, d = b;
#pragma unroll
    for (int q = 0; q < 16; q++) {
        ulonglong2 h0 = *(const ulonglong2*)(hp + 8 * q);
        ulonglong2 h1 = *(const ulonglong2*)(hp + 8 * q + 4);
        a = ffma2(h0.x, w[4 * q + 0], a);
        b = ffma2(h0.y, w[4 * q + 1], b);
        c = ffma2(h1.x, w[4 * q + 2], c);
        d = ffma2(h1.y, w[4 * q + 3], d);
    }
    float2 fa = unpack2(a), fb = unpack2(b), fc = unpack2(c), fd = unpack2(d);
    return ((fa.x + fa.y) + (fb.x + fb.y)) + ((fc.x + fc.y) + (fd.x + fd.y));
}

__global__ void __launch_bounds__(384, 1) phase2_kernel(
    const float* __restrict__ wzh, const float* __restrict__ wrh,
    const float* __restrict__ whh,
    float* __restrict__ hidden, float* __restrict__ hlast)
{
    __shared__ alignas(16) float hcur[2][Hq];   // gamma-scaled hidden state
    __shared__ alignas(16) float rh[2][Hq];     // r * h
    __shared__ alignas(16) float zs[2][Hq];     // z gate

    const int tid = threadIdx.x;
    const int g3 = tid >> 7;        // 0=z, 1=r, 2=h
    const int j = tid & 127;
    const int b0 = blockIdx.x * RPC;

    // register-resident weight column (packed over k)
    const float* W = (g3 == 0) ? wzh : (g3 == 1) ? wrh : whh;
    ull wreg[64];
#pragma unroll
    for (int kp = 0; kp < 64; kp++)
        wreg[kp] = pack2(W[(2 * kp) * Hq + j], W[(2 * kp + 1) * Hq + j]);

    if (tid < 2 * Hq) ((float*)hcur)[tid] = 0.f;

    const size_t base0 = (size_t)b0 * TH + j;        // (row0, t=0, j)
    const size_t base1 = base0 + TH;                 // (row1, t=0, j)

    // A regs: consumed at even slots; B regs: odd slots.
    float aA, aB, ghA = 1.f, ghB = 1.f;
    float hreg0 = 0.f, hreg1 = 0.f;                  // h-warps' private state
    if (g3 == 0)      { aA = g_Az[base0]; aB = g_Az[base1]; }
    else if (g3 == 1) { aA = g_Ar[base0]; aB = g_Ar[base1]; }
    else {
        aA = g_Ah[base1];  ghA = g_gh[base1 + Hq];   // consumed slot 2: (row1,t0)
        aB = g_Ah[base0];  ghB = g_gh[base0 + Hq];   // consumed slot 1: (row0,t0)
    }

    __syncthreads();

    for (int su = 0; su < 2 * Tq; su += 2) {
        const int thalf = su >> 1;          // t index for z/r in this pair

        // ================= even slot su: zr row0 / h row1 =================
        {
            float a_here = aA, gh_here = ghA;
            // prefetch into A regs (consumed at slot su+2)
            if (g3 == 0) {
                int t = thalf + 1; if (t > Tq - 1) t = Tq - 1;
                aA = g_Az[base0 + (size_t)t * Hq];
            } else if (g3 == 1) {
                int t = thalf + 1; if (t > Tq - 1) t = Tq - 1;
                aA = g_Ar[base0 + (size_t)t * Hq];
            } else {
                size_t ix = base1 + (size_t)thalf * Hq;     // (row1, thalf)
                aA = g_Ah[ix];
                ghA = (thalf + 1 < Tq) ? g_gh[ix + Hq] : 1.f;
            }

            if (g3 == 0) {
                float sum = dot1(&hcur[0][0], wreg, a_here);
                zs[0][j] = fast_sigmoid(sum);
            } else if (g3 == 1) {
                float hj = hcur[0][j];                      // hoisted load
                float sum = dot1(&hcur[0][0], wreg, a_here);
                rh[0][j] = fast_sigmoid(sum) * hj;
            } else if (su >= 2) {
                // h~/update for (row1, t = thalf-1)
                float sum = dot1(&rh[1][0], wreg, a_here);
                float ht = fmaf(2.f, fast_sigmoid(2.f * sum), -1.f);
                float hn = fmaf(zs[1][j], ht - hreg1, hreg1);
                hidden[base1 + (size_t)(thalf - 1) * Hq] = hn;
                hreg1 = hn * gh_here;                       // pre-scale gamma(t+1)
                hcur[1][j] = hreg1;
            }
        }
        __syncthreads();

        // ================= odd slot su+1: zr row1 / h row0 =================
        {
            float a_here = aB, gh_here = ghB;
            if (g3 == 0) {
                int t = thalf + 1; if (t > Tq - 1) t = Tq - 1;
                aB = g_Az[base1 + (size_t)t * Hq];
            } else if (g3 == 1) {
                int t = thalf + 1; if (t > Tq - 1) t = Tq - 1;
                aB = g_Ar[base1 + (size_t)t * Hq];
            } else {
                int t = thalf + 1; if (t > Tq - 1) t = Tq - 1;  // (row0, thalf+1)
                size_t ix = base0 + (size_t)t * Hq;
                aB = g_Ah[ix];
                ghB = (t + 1 < Tq) ? g_gh[ix + Hq] : 1.f;
            }

            if (g3 == 0) {
                float sum = dot1(&hcur[1][0], wreg, a_here);
                zs[1][j] = fast_sigmoid(sum);
            } else if (g3 == 1) {
                float hj = hcur[1][j];
                float sum = dot1(&hcur[1][0], wreg, a_here);
                rh[1][j] = fast_sigmoid(sum) * hj;
            } else {
                // h~/update for (row0, t = thalf)
                float sum = dot1(&rh[0][0], wreg, a_here);
                float ht = fmaf(2.f, fast_sigmoid(2.f * sum), -1.f);
                float hn = fmaf(zs[0][j], ht - hreg0, hreg0);
                hidden[base0 + (size_t)thalf * Hq] = hn;
                hreg0 = hn * gh_here;
                hcur[0][j] = hreg0;
            }
        }
        __syncthreads();
    }

    // final slot 2*Tq: only h-warps — (row1, t = Tq-1), gamma = 1
    if (g3 == 2) {
        float sum = dot1(&rh[1][0], wreg, aA);
        float ht = fmaf(2.f, fast_sigmoid(2.f * sum), -1.f);
        float hn = fmaf(zs[1][j], ht - hreg1, hreg1);
        hidden[base1 + (size_t)(Tq - 1) * Hq] = hn;
        hreg1 = hn;

        // hreg0 finished unscaled at the last odd slot (ghB clamped to 1)
        hlast[(size_t)b0 * Hq + j]       = hreg0;
        hlast[(size_t)(b0 + 1) * Hq + j] = hreg1;
    }
}

// ---------------- launch ----------------------------------------------------
extern "C" void kernel_launch(void* const* d_in, const int* in_sizes, int n_in,
                              void* d_out, int out_size) {
    const float* values = (const float*)d_in[0];
    const float* masks  = (const float*)d_in[1];
    const float* deltas = (const float*)d_in[2];
    const float* emp    = (const float*)d_in[3];
    const float* xlocf  = (const float*)d_in[4];
    const float* wgx    = (const float*)d_in[5];
    const float* wgh    = (const float*)d_in[6];
    const float* wrx    = (const float*)d_in[7];
    const float* wrh    = (const float*)d_in[8];
    const float* wrm    = (const float*)d_in[9];
    const float* wzx    = (const float*)d_in[10];
    const float* wzh    = (const float*)d_in[11];
    const float* wzm    = (const float*)d_in[12];
    const float* whx    = (const float*)d_in[13];
    const float* whh    = (const float*)d_in[14];
    const float* whm    = (const float*)d_in[15];
    const float* bgx    = (const float*)d_in[16];
    const float* bgh    = (const float*)d_in[17];
    const float* br     = (const float*)d_in[18];
    const float* bz     = (const float*)d_in[19];
    const float* bh     = (const float*)d_in[20];

    float* out = (float*)d_out;
    float* hidden = out;                              // [B, T, H]
    float* hlast = out + (size_t)Bq * Tq * Hq;        // [B, H]

    phase1_kernel<<<NROW / RPB, 512>>>(values, masks, deltas, emp, xlocf,
                                       wgx, bgx, wgh, bgh,
                                       wzx, wzm, bz,
                                       wrx, wrm, br,
                                       whx, whm, bh);

    phase2_kernel<<<GRID2, 384>>>(wzh, wrh, whh, hidden, hlast);
}

// round 10
// speedup vs baseline: 1.1792x; 1.1792x over previous
#include <cuda_runtime.h>
#include <cuda_bf16.h>
#include <cstdint>
#include <cstddef>

#define Bq 256
#define Tq 512
#define Dq 64
#define Hq 128
#define NROW (Bq * Tq)
#define TH ((size_t)Tq * Hq)

typedef unsigned long long ull;

// ---------------- packed f32x2 helpers -------------------------------------
__device__ __forceinline__ ull ffma2(ull a, ull b, ull c) {
    ull d;
    asm("fma.rn.f32x2 %0, %1, %2, %3;" : "=l"(d) : "l"(a), "l"(b), "l"(c));
    return d;
}
__device__ __forceinline__ ull pack2(float lo, float hi) {
    ull d;
    asm("mov.b64 %0, {%1, %2};" : "=l"(d) : "f"(lo), "f"(hi));
    return d;
}
__device__ __forceinline__ float2 unpack2(ull v) {
    float2 r;
    asm("mov.b64 {%0, %1}, %2;" : "=f"(r.x), "=f"(r.y) : "l"(v));
    return r;
}
__device__ __forceinline__ float fast_sigmoid(float x) {
    return __fdividef(1.f, 1.f + __expf(-x));
}

// ---------------- scratch (device globals; no runtime allocation) ----------
__device__ float g_Az[(size_t)NROW * Hq];
__device__ float g_Ar[(size_t)NROW * Hq];
__device__ float g_Ah[(size_t)NROW * Hq];
__device__ float g_gh[(size_t)NROW * Hq];

// ---------------- Phase 1: imputation + input projections ------------------
// 64 rows per CTA, 512 threads (16 warps -> 4/SMSP). thread = (j, quarter).
// Each thread computes 16 rows (8 f32x2 row-pairs) for its output column j.
// (Measured 458 us in round-9 bench.)
#define RPB 64

__global__ void __launch_bounds__(512) phase1_kernel(
    const float* __restrict__ values, const float* __restrict__ masks,
    const float* __restrict__ deltas, const float* __restrict__ emp,
    const float* __restrict__ xlocf,
    const float* __restrict__ wgx, const float* __restrict__ bgx,
    const float* __restrict__ wgh, const float* __restrict__ bgh,
    const float* __restrict__ wzx, const float* __restrict__ wzm, const float* __restrict__ bz,
    const float* __restrict__ wrx, const float* __restrict__ wrm, const float* __restrict__ br,
    const float* __restrict__ whx, const float* __restrict__ whm, const float* __restrict__ bh)
{
    // [k][r] layout, row stride 64 floats (256B). 3 x 16KB = 48KB static.
    __shared__ alignas(16) float sx[Dq * RPB];
    __shared__ alignas(16) float smm[Dq * RPB];
    __shared__ alignas(16) float sd[Dq * RPB];

    const int tid = threadIdx.x;
    const int row0 = blockIdx.x * RPB;

    // load + impute (coalesced over k); element r of row k at sx[k*64 + r]
    for (int i = tid; i < RPB * Dq; i += 512) {
        int r = i >> 6, k = i & 63;
        size_t g = (size_t)(row0 + r) * Dq + k;
        float x = values[g], m = masks[g], dl = deltas[g], xl = xlocf[g];
        float gx = __expf(-fmaxf(fmaf(wgx[k], dl, bgx[k]), 0.f));
        float xi = m * x + (1.f - m) * (gx * xl + (1.f - gx) * emp[k]);
        sx[(k << 6) + r] = xi;
        smm[(k << 6) + r] = m;
        sd[(k << 6) + r] = dl;
    }
    __syncthreads();

    const int j = tid & 127;
    const int quarter = tid >> 7;       // which 16-row quarter
    const int fofs = quarter * 16;      // float offset within a smem row

    ull accZ[8], accR[8], accH[8], accG[8];
    {
        float bzv = bz[j], brv = br[j], bhv = bh[j], bgv = bgh[j];
#pragma unroll
        for (int p = 0; p < 8; p++) {
            accZ[p] = pack2(bzv, bzv);
            accR[p] = pack2(brv, brv);
            accH[p] = pack2(bhv, bhv);
            accG[p] = pack2(bgv, bgv);
        }
    }

#pragma unroll 4
    for (int k = 0; k < Dq; k++) {
        int wi = k * Hq + j;
        ull wgh2 = pack2(wgh[wi], wgh[wi]);
        ull wzx2 = pack2(wzx[wi], wzx[wi]);
        ull wzm2 = pack2(wzm[wi], wzm[wi]);
        ull wrx2 = pack2(wrx[wi], wrx[wi]);
        ull wrm2 = pack2(wrm[wi], wrm[wi]);
        ull whx2 = pack2(whx[wi], whx[wi]);
        ull whm2 = pack2(whm[wi], whm[wi]);
        const ulonglong2* x2 = (const ulonglong2*)(sx + (k << 6) + fofs);
        const ulonglong2* m2 = (const ulonglong2*)(smm + (k << 6) + fofs);
        const ulonglong2* d2 = (const ulonglong2*)(sd + (k << 6) + fofs);
#pragma unroll
        for (int q = 0; q < 4; q++) {
            ulonglong2 xv = x2[q];
            ulonglong2 mv = m2[q];
            ulonglong2 dv = d2[q];
            accG[2 * q]     = ffma2(dv.x, wgh2, accG[2 * q]);
            accG[2 * q + 1] = ffma2(dv.y, wgh2, accG[2 * q + 1]);
            accZ[2 * q]     = ffma2(xv.x, wzx2, accZ[2 * q]);
            accZ[2 * q + 1] = ffma2(xv.y, wzx2, accZ[2 * q + 1]);
            accR[2 * q]     = ffma2(xv.x, wrx2, accR[2 * q]);
            accR[2 * q + 1] = ffma2(xv.y, wrx2, accR[2 * q + 1]);
            accH[2 * q]     = ffma2(xv.x, whx2, accH[2 * q]);
            accH[2 * q + 1] = ffma2(xv.y, whx2, accH[2 * q + 1]);
            accZ[2 * q]     = ffma2(mv.x, wzm2, accZ[2 * q]);
            accZ[2 * q + 1] = ffma2(mv.y, wzm2, accZ[2 * q + 1]);
            accR[2 * q]     = ffma2(mv.x, wrm2, accR[2 * q]);
            accR[2 * q + 1] = ffma2(mv.y, wrm2, accR[2 * q + 1]);
            accH[2 * q]     = ffma2(mv.x, whm2, accH[2 * q]);
            accH[2 * q + 1] = ffma2(mv.y, whm2, accH[2 * q + 1]);
        }
    }

#pragma unroll
    for (int p = 0; p < 8; p++) {
        int r0 = quarter * 16 + 2 * p;
        size_t o0 = (size_t)(row0 + r0) * Hq + j;
        size_t o1 = o0 + Hq;
        float2 vz = unpack2(accZ[p]);
        float2 vr = unpack2(accR[p]);
        float2 vh = unpack2(accH[p]);
        float2 vg = unpack2(accG[p]);
        g_Az[o0] = vz.x;  g_Az[o1] = vz.y;
        g_Ar[o0] = vr.x;  g_Ar[o1] = vr.y;
        g_Ah[o0] = vh.x;  g_Ah[o1] = vh.y;
        g_gh[o0] = __expf(-fmaxf(vg.x, 0.f));
        g_gh[o1] = __expf(-fmaxf(vg.y, 0.f));
    }
}

// ---------------- Phase 2: persistent recurrence (pipelined over rows) -----
// R7 shift-register pipeline, measured 682.752 us. 128 CTAs x 384 threads.
// Warp groups: g=0 -> z, g=1 -> r, g=2 -> h; weights register-resident.
// Slot schedule (one barrier per slot):
//   slot s: z/r warps compute gates for index s = (row = s&1, t = s>>1)
//           h warps compute h~/update for index s-1                  [s >= 1]
// z/r consume index s -> init a_c=idx0, a_n=idx1, prefetch at s loads
// idx(s+2). h consumes index s-1 -> init a_n=idx0 (a_c unused), prefetch at
// s loads idx(s+1). Gamma-scaling folded into the h epilogue.
#define RPC 2
#define GRID2 (Bq / RPC)

__device__ __forceinline__ float dot1(const float* __restrict__ hp,
                                      const ull* __restrict__ w, float init)
{
    ull a = pack2(init, 0.f);
    ull b = pack2(0.f, 0.f);
    ull c = b, d = b;
#pragma unroll
    for (int q = 0; q < 16; q++) {
        ulonglong2 h0 = *(const ulonglong2*)(hp + 8 * q);
        ulonglong2 h1 = *(const ulonglong2*)(hp + 8 * q + 4);
        a = ffma2(h0.x, w[4 * q + 0], a);
        b = ffma2(h0.y, w[4 * q + 1], b);
        c = ffma2(h1.x, w[4 * q + 2], c);
        d = ffma2(h1.y, w[4 * q + 3], d);
    }
    float2 fa = unpack2(a), fb = unpack2(b), fc = unpack2(c), fd = unpack2(d);
    return ((fa.x + fa.y) + (fb.x + fb.y)) + ((fc.x + fc.y) + (fd.x + fd.y));
}

__global__ void __launch_bounds__(384, 1) phase2_kernel(
    const float* __restrict__ wzh, const float* __restrict__ wrh,
    const float* __restrict__ whh,
    float* __restrict__ hidden, float* __restrict__ hlast)
{
    __shared__ alignas(16) float hcur[2][Hq];   // gamma-scaled hidden state
    __shared__ alignas(16) float rh[2][Hq];     // r * h
    __shared__ alignas(16) float zs[2][Hq];     // z gate

    const int tid = threadIdx.x;
    const int g3 = tid >> 7;        // 0=z, 1=r, 2=h
    const int j = tid & 127;
    const int b0 = blockIdx.x * RPC;

    // register-resident weight column (packed over k)
    const float* W = (g3 == 0) ? wzh : (g3 == 1) ? wrh : whh;
    ull wreg[64];
#pragma unroll
    for (int kp = 0; kp < 64; kp++)
        wreg[kp] = pack2(W[(2 * kp) * Hq + j], W[(2 * kp + 1) * Hq + j]);

    if (tid < 2 * Hq) ((float*)hcur)[tid] = 0.f;

    const size_t r0base = (size_t)b0 * TH + j;       // (row0, t=0)
    const size_t r1base = r0base + TH;               // (row1, t=0)

    float a_c, a_n, gh_c = 1.f, gh_n = 1.f;
    if (g3 == 0)      { a_c = g_Az[r0base]; a_n = g_Az[r1base]; }
    else if (g3 == 1) { a_c = g_Ar[r0base]; a_n = g_Ar[r1base]; }
    else {
        // h consumes idx0 at slot 1 -> that value must sit in a_n at init.
        a_c = 0.f;           gh_c = 1.f;                    // unused (slot 0)
        a_n = g_Ah[r0base];  gh_n = g_gh[r0base + Hq];      // gamma(row0, t=1)
    }

    __syncthreads();

    const int NSLOT = 2 * Tq;   // slots 0..NSLOT inclusive
    for (int s = 0; s <= NSLOT; s++) {
        // ---- prefetch (hidden behind this slot's dot)
        float a_nn = 0.f, gh_nn = 1.f;
        if (g3 < 2) {
            // feeds slot s+2 -> index s+2 = (row = s&1, t = (s>>1)+1)
            if (s + 2 < NSLOT) {
                int row = s & 1, t = (s >> 1) + 1;
                size_t ix = (size_t)(b0 + row) * TH + (size_t)t * Hq + j;
                a_nn = (g3 == 0) ? g_Az[ix] : g_Ar[ix];
            }
        } else {
            // feeds slot s+2 -> h consumes index s+1 there
            if (s + 1 < NSLOT) {
                int row = (s + 1) & 1, t = (s + 1) >> 1;
                size_t ix = (size_t)(b0 + row) * TH + (size_t)t * Hq + j;
                a_nn = g_Ah[ix];
                gh_nn = (t + 1 < Tq) ? g_gh[ix + Hq] : 1.f;
            }
        }

        if (g3 < 2) {
            if (s < NSLOT) {
                int row = s & 1;
                float sum = dot1(&hcur[row][0], wreg, a_c);
                float sg = fast_sigmoid(sum);
                if (g3 == 0) zs[row][j] = sg;
                else         rh[row][j] = sg * hcur[row][j];
            }
        } else {
            if (s >= 1) {
                int row = (s - 1) & 1;
                int t = (s - 1) >> 1;
                float sum = dot1(&rh[row][0], wreg, a_c);
                // tanh(x) = 2*sigmoid(2x) - 1  (overflow-safe)
                float ht = fmaf(2.f, fast_sigmoid(2.f * sum), -1.f);
                float hv = hcur[row][j];
                float hn = fmaf(zs[row][j], ht - hv, hv);
                hidden[(size_t)(b0 + row) * TH + (size_t)t * Hq + j] = hn;
                hcur[row][j] = hn * gh_c;   // pre-scale by gamma(t+1)
            }
        }

        a_c = a_n;  a_n = a_nn;
        gh_c = gh_n; gh_n = gh_nn;
        __syncthreads();
    }

    if (g3 == 2) {
        // hcur holds unscaled final h (last gamma multiplier was 1.0)
        hlast[(size_t)b0 * Hq + j]       = hcur[0][j];
        hlast[(size_t)(b0 + 1) * Hq + j] = hcur[1][j];
    }
}

// ---------------- launch ----------------------------------------------------
extern "C" void kernel_launch(void* const* d_in, const int* in_sizes, int n_in,
                              void* d_out, int out_size) {
    const float* values = (const float*)d_in[0];
    const float* masks  = (const float*)d_in[1];
    const float* deltas = (const float*)d_in[2];
    const float* emp    = (const float*)d_in[3];
    const float* xlocf  = (const float*)d_in[4];
    const float* wgx    = (const float*)d_in[5];
    const float* wgh    = (const float*)d_in[6];
    const float* wrx    = (const float*)d_in[7];
    const float* wrh    = (const float*)d_in[8];
    const float* wrm    = (const float*)d_in[9];
    const float* wzx    = (const float*)d_in[10];
    const float* wzh    = (const float*)d_in[11];
    const float* wzm    = (const float*)d_in[12];
    const float* whx    = (const float*)d_in[13];
    const float* whh    = (const float*)d_in[14];
    const float* whm    = (const float*)d_in[15];
    const float* bgx    = (const float*)d_in[16];
    const float* bgh    = (const float*)d_in[17];
    const float* br     = (const float*)d_in[18];
    const float* bz     = (const float*)d_in[19];
    const float* bh     = (const float*)d_in[20];

    float* out = (float*)d_out;
    float* hidden = out;                              // [B, T, H]
    float* hlast = out + (size_t)Bq * Tq * Hq;        // [B, H]

    phase1_kernel<<<NROW / RPB, 512>>>(values, masks, deltas, emp, xlocf,
                                       wgx, bgx, wgh, bgh,
                                       wzx, wzm, bz,
                                       wrx, wrm, br,
                                       whx, whm, bh);

    phase2_kernel<<<GRID2, 384>>>(wzh, wrh, whh, hidden, hlast);
}